// round 7
// baseline (speedup 1.0000x reference)
#include <cuda_runtime.h>
#include <cuda_bf16.h>
#include <math.h>

#define BN 131072
#define D  256

// ---------------- scratch (device globals: allocation-free) ----------------
__device__ float       g_h1[(size_t)BN * D];
__device__ float       g_h2[(size_t)BN * D];
__device__ float       g_mu[3][BN];
__device__ float       g_rstd[3][BN];
__device__ unsigned    g_gamma[3];
__device__ float       g_beta[3];
__device__ signed char g_wb[3][D * D];

// ---------------- init: zero the gamma accumulators -----------------------
__global__ void init_kernel() {
    if (threadIdx.x < 3) g_gamma[threadIdx.x] = 0u;
}

// ---------------- weight prep: alpha/beta + sign-pack to int8 -------------
__global__ void __launch_bounds__(1024) wprep_kernel(const float* __restrict__ W1,
                                                     const float* __restrict__ W2,
                                                     const float* __restrict__ W3) {
    const float* W = blockIdx.x == 0 ? W1 : (blockIdx.x == 1 ? W2 : W3);
    __shared__ float ps[32], pa[32];
    __shared__ float s_alpha;
    int tid = threadIdx.x;
    float s = 0.f, sa = 0.f;
    for (int i = tid; i < D * D; i += 1024) {
        float w = W[i];
        s += w; sa += fabsf(w);
    }
#pragma unroll
    for (int o = 16; o; o >>= 1) {
        s  += __shfl_xor_sync(0xffffffffu, s,  o);
        sa += __shfl_xor_sync(0xffffffffu, sa, o);
    }
    if ((tid & 31) == 0) { ps[tid >> 5] = s; pa[tid >> 5] = sa; }
    __syncthreads();
    if (tid == 0) {
        float ts = 0.f, ta = 0.f;
        for (int i = 0; i < 32; i++) { ts += ps[i]; ta += pa[i]; }  // fixed order
        float alpha = ts / 65536.0f;
        float beta  = fmaxf(ta / 65536.0f, 1e-8f);
        g_beta[blockIdx.x] = beta;
        s_alpha = alpha;
    }
    __syncthreads();
    float alpha = s_alpha;
    unsigned* dst = (unsigned*)g_wb[blockIdx.x];
    for (int w = tid; w < D * D / 4; w += 1024) {
        float4 v = *(const float4*)(W + (size_t)w * 4);
        unsigned b0 = ((v.x - alpha) > 0.f) ? 1u : 0xFFu;
        unsigned b1 = ((v.y - alpha) > 0.f) ? 1u : 0xFFu;
        unsigned b2 = ((v.z - alpha) > 0.f) ? 1u : 0xFFu;
        unsigned b3 = ((v.w - alpha) > 0.f) ? 1u : 0xFFu;
        dst[w] = b0 | (b1 << 8) | (b2 << 16) | (b3 << 24);
    }
}

// ---------------- stats for x: per-row mu/rstd + global gamma[0] ----------
__global__ void __launch_bounds__(256) stats_kernel(const float* __restrict__ x) {
    __shared__ unsigned sg;
    int tid = threadIdx.x;
    if (tid == 0) sg = 0u;
    __syncthreads();
    int warp = tid >> 5, lane = tid & 31;
    size_t row = (size_t)blockIdx.x * 8 + warp;
    const float* xr = x + row * D;
    float4 a = *(const float4*)(xr + lane * 4);
    float4 b = *(const float4*)(xr + 128 + lane * 4);
    float s = ((a.x + a.y) + (a.z + a.w)) + ((b.x + b.y) + (b.z + b.w));
#pragma unroll
    for (int o = 16; o; o >>= 1) s += __shfl_xor_sync(0xffffffffu, s, o);
    float mu = s * (1.0f / 256.0f);
    float ss = 0.f, mx = 0.f, d;
    d = a.x - mu; ss += d * d; mx = fmaxf(mx, fabsf(d));
    d = a.y - mu; ss += d * d; mx = fmaxf(mx, fabsf(d));
    d = a.z - mu; ss += d * d; mx = fmaxf(mx, fabsf(d));
    d = a.w - mu; ss += d * d; mx = fmaxf(mx, fabsf(d));
    d = b.x - mu; ss += d * d; mx = fmaxf(mx, fabsf(d));
    d = b.y - mu; ss += d * d; mx = fmaxf(mx, fabsf(d));
    d = b.z - mu; ss += d * d; mx = fmaxf(mx, fabsf(d));
    d = b.w - mu; ss += d * d; mx = fmaxf(mx, fabsf(d));
#pragma unroll
    for (int o = 16; o; o >>= 1) {
        ss += __shfl_xor_sync(0xffffffffu, ss, o);
        mx  = fmaxf(mx, __shfl_xor_sync(0xffffffffu, mx, o));
    }
    float rsd = 1.0f / sqrtf(ss * (1.0f / 256.0f) + 1e-5f);
    if (lane == 0) {
        g_mu[0][row]   = mu;
        g_rstd[0][row] = rsd;
        atomicMax(&sg, __float_as_uint(mx * rsd));  // values >= 0: uint order == float order
    }
    __syncthreads();
    if (tid == 0) atomicMax(&g_gamma[0], sg);
}

// ---------------- fused layer: quantize -> s8 MMA -> scale/relu -> next-LN stats
// CTA: 128 rows x 256 cols, K=256.  512 thr = 16 warps (4M x 4N), warp tile 32x64.
template <int L>
__global__ void __launch_bounds__(512, 1) layer_kernel(const float* __restrict__ in_p,
                                                       float* __restrict__ out_p) {
    constexpr bool LAST = (L == 2);
    const float* in  = (L == 0) ? in_p : (L == 1 ? (const float*)g_h1 : (const float*)g_h2);
    float*       out = LAST ? out_p : (L == 0 ? g_h1 : g_h2);

    extern __shared__ unsigned smem[];
    unsigned* Asm    = smem;                          // 128*68 words (pitch 272B)
    unsigned* Bsm    = Asm + 128 * 68;                // 256*68 words
    float*    rsum_p = (float*)(Bsm + 256 * 68);      // [4][128]
    float*    rsq_p  = rsum_p + 4 * 128;              // [4][128]
    unsigned* rmax   = (unsigned*)(rsq_p + 4 * 128);  // [128]
    float*    mu_s   = (float*)(rmax + 128);          // [128]
    float*    rstd_s = mu_s + 128;                    // [128]
    unsigned* sgmax  = (unsigned*)(rstd_s + 128);     // [1]

    int tid = threadIdx.x;
    float gamma = fmaxf(__uint_as_float(g_gamma[L]), 1e-8f);
    float qs = 127.0f / gamma;
    int row0 = blockIdx.x * 128;
    const float* mu_in   = g_mu[L];
    const float* rstd_in = g_rstd[L];

    // --- load + LN + quantize A into smem (int8, 4/word) ---
    for (int w = tid; w < 128 * 64; w += 512) {
        int r = w >> 6, kw = w & 63;
        int grow = row0 + r;
        float4 v = *(const float4*)(in + (size_t)grow * D + kw * 4);
        float mu = mu_in[grow], rsd = rstd_in[grow];
        float xn0 = (v.x - mu) * rsd;
        float xn1 = (v.y - mu) * rsd;
        float xn2 = (v.z - mu) * rsd;
        float xn3 = (v.w - mu) * rsd;
        int q0 = __float2int_rn(fminf(fmaxf(xn0 * qs, -127.f), 127.f));
        int q1 = __float2int_rn(fminf(fmaxf(xn1 * qs, -127.f), 127.f));
        int q2 = __float2int_rn(fminf(fmaxf(xn2 * qs, -127.f), 127.f));
        int q3 = __float2int_rn(fminf(fmaxf(xn3 * qs, -127.f), 127.f));
        Asm[r * 68 + kw] = (q0 & 0xFF) | ((q1 & 0xFF) << 8) | ((q2 & 0xFF) << 16) | ((q3 & 0xFF) << 24);
    }
    // --- load B (binary weights, int8) ---
    const unsigned* Bw = (const unsigned*)g_wb[L];
    for (int w = tid; w < 256 * 64; w += 512)
        Bsm[(w >> 6) * 68 + (w & 63)] = Bw[w];
    if (!LAST && tid < 128) rmax[tid] = 0u;
    if (tid == 0) *sgmax = 0u;
    __syncthreads();

    int lane = tid & 31, warp = tid >> 5;
    int wm = warp & 3, wn = warp >> 2;      // 4 M-groups of 32 rows, 4 N-groups of 64 cols
    int qrow = lane >> 2, tig = lane & 3;

    int acc[2][8][4];
#pragma unroll
    for (int i = 0; i < 2; i++)
#pragma unroll
        for (int j = 0; j < 8; j++)
#pragma unroll
            for (int r = 0; r < 4; r++) acc[i][j][r] = 0;

#pragma unroll
    for (int kk = 0; kk < 8; kk++) {
        unsigned a[2][4];
#pragma unroll
        for (int i = 0; i < 2; i++) {
            int rbase = wm * 32 + i * 16 + qrow;
            a[i][0] = Asm[rbase * 68 + kk * 8 + tig];
            a[i][1] = Asm[(rbase + 8) * 68 + kk * 8 + tig];
            a[i][2] = Asm[rbase * 68 + kk * 8 + 4 + tig];
            a[i][3] = Asm[(rbase + 8) * 68 + kk * 8 + 4 + tig];
        }
#pragma unroll
        for (int j = 0; j < 8; j++) {
            int n = wn * 64 + j * 8 + qrow;
            unsigned b0 = Bsm[n * 68 + kk * 8 + tig];
            unsigned b1 = Bsm[n * 68 + kk * 8 + 4 + tig];
#pragma unroll
            for (int i = 0; i < 2; i++) {
                asm volatile(
                    "mma.sync.aligned.m16n8k32.row.col.s32.s8.s8.s32 "
                    "{%0,%1,%2,%3}, {%4,%5,%6,%7}, {%8,%9}, {%0,%1,%2,%3};\n"
                    : "+r"(acc[i][j][0]), "+r"(acc[i][j][1]),
                      "+r"(acc[i][j][2]), "+r"(acc[i][j][3])
                    : "r"(a[i][0]), "r"(a[i][1]), "r"(a[i][2]), "r"(a[i][3]),
                      "r"(b0), "r"(b1));
            }
        }
    }

    float beta = g_beta[L];
    float oscale = beta * gamma / 127.0f;

    // --- epilogue: scale (+relu), store, fixed-order row sums for next LN ---
#pragma unroll
    for (int i = 0; i < 2; i++) {
#pragma unroll
        for (int hi = 0; hi < 2; hi++) {
            int lr = wm * 32 + i * 16 + hi * 8 + qrow;
            int grow = row0 + lr;
            float s1 = 0.f, s2 = 0.f;
#pragma unroll
            for (int j = 0; j < 8; j++) {
                float v0 = (float)acc[i][j][hi * 2 + 0] * oscale;
                float v1 = (float)acc[i][j][hi * 2 + 1] * oscale;
                if (!LAST) { v0 = fmaxf(v0, 0.f); v1 = fmaxf(v1, 0.f); }
                int col = wn * 64 + j * 8 + tig * 2;
                *(float2*)(out + (size_t)grow * D + col) = make_float2(v0, v1);
                s1 += v0 + v1;
                s2 += v0 * v0 + v1 * v1;
            }
            if (!LAST) {
                s1 += __shfl_xor_sync(0xffffffffu, s1, 1);
                s1 += __shfl_xor_sync(0xffffffffu, s1, 2);
                s2 += __shfl_xor_sync(0xffffffffu, s2, 1);
                s2 += __shfl_xor_sync(0xffffffffu, s2, 2);
                if (tig == 0) { rsum_p[wn * 128 + lr] = s1; rsq_p[wn * 128 + lr] = s2; }
            }
        }
    }
    if (LAST) return;

    __syncthreads();
    if (tid < 128) {
        float s1 = ((rsum_p[tid] + rsum_p[128 + tid]) + (rsum_p[256 + tid] + rsum_p[384 + tid]));
        float s2 = ((rsq_p[tid]  + rsq_p[128 + tid])  + (rsq_p[256 + tid]  + rsq_p[384 + tid]));
        float mu  = s1 * (1.0f / 256.0f);
        float var = fmaxf(s2 * (1.0f / 256.0f) - mu * mu, 0.0f);
        float rsd = 1.0f / sqrtf(var + 1e-5f);
        mu_s[tid] = mu; rstd_s[tid] = rsd;
        g_mu[L + 1][row0 + tid]   = mu;
        g_rstd[L + 1][row0 + tid] = rsd;
    }
    __syncthreads();

    // --- absmax of normalized next-layer input (recompute h from acc) ---
#pragma unroll
    for (int i = 0; i < 2; i++) {
#pragma unroll
        for (int hi = 0; hi < 2; hi++) {
            int lr = wm * 32 + i * 16 + hi * 8 + qrow;
            float mu = mu_s[lr];
            float mx = 0.f;
#pragma unroll
            for (int j = 0; j < 8; j++) {
                float v0 = fmaxf((float)acc[i][j][hi * 2 + 0] * oscale, 0.f);
                float v1 = fmaxf((float)acc[i][j][hi * 2 + 1] * oscale, 0.f);
                mx = fmaxf(mx, fabsf(v0 - mu));
                mx = fmaxf(mx, fabsf(v1 - mu));
            }
            mx = fmaxf(mx, __shfl_xor_sync(0xffffffffu, mx, 1));
            mx = fmaxf(mx, __shfl_xor_sync(0xffffffffu, mx, 2));
            if (tig == 0) atomicMax(&rmax[lr], __float_as_uint(mx));
        }
    }
    __syncthreads();
    if (tid < 128) {
        unsigned gu = __float_as_uint(__uint_as_float(rmax[tid]) * rstd_s[tid]);
#pragma unroll
        for (int o = 16; o; o >>= 1) gu = max(gu, __shfl_xor_sync(0xffffffffu, gu, o));
        if ((tid & 31) == 0) atomicMax(sgmax, gu);
    }
    __syncthreads();
    if (tid == 0) atomicMax(&g_gamma[L + 1], *sgmax);
}

// ---------------- launch ----------------
extern "C" void kernel_launch(void* const* d_in, const int* in_sizes, int n_in,
                              void* d_out, int out_size) {
    const float* x  = (const float*)d_in[0];
    const float* W1 = (const float*)d_in[1];
    const float* W2 = (const float*)d_in[2];
    const float* W3 = (const float*)d_in[3];
    float* out = (float*)d_out;

    constexpr int SMEM = (128 * 68 + 256 * 68 + 4 * 128 * 2 + 128 * 3 + 1) * 4;  // 110084 B
    cudaFuncSetAttribute(layer_kernel<0>, cudaFuncAttributeMaxDynamicSharedMemorySize, SMEM);
    cudaFuncSetAttribute(layer_kernel<1>, cudaFuncAttributeMaxDynamicSharedMemorySize, SMEM);
    cudaFuncSetAttribute(layer_kernel<2>, cudaFuncAttributeMaxDynamicSharedMemorySize, SMEM);

    init_kernel<<<1, 32>>>();
    wprep_kernel<<<3, 1024>>>(W1, W2, W3);
    stats_kernel<<<BN / 8, 256>>>(x);
    layer_kernel<0><<<BN / 128, 512, SMEM>>>(x, nullptr);
    layer_kernel<1><<<BN / 128, 512, SMEM>>>(nullptr, nullptr);
    layer_kernel<2><<<BN / 128, 512, SMEM>>>(nullptr, out);
}

// round 11
// speedup vs baseline: 1.6025x; 1.6025x over previous
#include <cuda_runtime.h>
#include <cuda_bf16.h>
#include <math.h>
#include <stdint.h>

#define BN 131072
#define DD 256

// ---------------- scratch (device globals: allocation-free) ----------------
__device__ __align__(16) short       g_hs1[(size_t)BN * DD];   // layer0 out (int16, exact)
__device__ __align__(16) short       g_hs2[(size_t)BN * DD];   // layer1 out
__device__ float                     g_mu[3][BN];
__device__ float                     g_rstd[3][BN];
__device__ unsigned                  g_gamma[3];
__device__ float                     g_beta[3];
__device__ __align__(16) signed char g_wb[3][DD * DD];         // +-1 int8, swizzled [n][k] layout

__device__ __forceinline__ uint32_t smem_u32(const void* p) {
    uint32_t a;
    asm("{ .reg .u64 t; cvta.to.shared.u64 t, %1; cvt.u32.u64 %0, t; }" : "=r"(a) : "l"(p));
    return a;
}

// ---------------- init ----------------
__global__ void init_kernel() {
    if (threadIdx.x < 3) g_gamma[threadIdx.x] = 0u;
}

// ---------------- weight prep: alpha/beta + sign -> swizzled int8 ---------
// Layout: row n (256 B of k), chunk c (16B) stored at chunk (c ^ (n&7)).
__global__ void __launch_bounds__(1024) wprep_kernel(const float* __restrict__ W1,
                                                     const float* __restrict__ W2,
                                                     const float* __restrict__ W3) {
    const float* W = blockIdx.x == 0 ? W1 : (blockIdx.x == 1 ? W2 : W3);
    __shared__ float ps[32], pa[32];
    __shared__ float s_alpha;
    int tid = threadIdx.x;
    float s = 0.f, sa = 0.f;
    for (int i = tid; i < DD * DD; i += 1024) {
        float w = W[i];
        s += w; sa += fabsf(w);
    }
#pragma unroll
    for (int o = 16; o; o >>= 1) {
        s  += __shfl_xor_sync(0xffffffffu, s,  o);
        sa += __shfl_xor_sync(0xffffffffu, sa, o);
    }
    if ((tid & 31) == 0) { ps[tid >> 5] = s; pa[tid >> 5] = sa; }
    __syncthreads();
    if (tid == 0) {
        float ts = 0.f, ta = 0.f;
        for (int i = 0; i < 32; i++) { ts += ps[i]; ta += pa[i]; }  // fixed order
        float alpha = ts / 65536.0f;
        g_beta[blockIdx.x] = fmaxf(ta / 65536.0f, 1e-8f);
        s_alpha = alpha;
    }
    __syncthreads();
    float alpha = s_alpha;
    signed char* wb = g_wb[blockIdx.x];
    for (int i = tid; i < DD * DD; i += 1024) {
        int n = i >> 8, k = i & 255;
        signed char v = ((W[i] - alpha) > 0.f) ? (signed char)1 : (signed char)-1;
        unsigned off = (unsigned)n * 256u + ((((unsigned)k >> 4) ^ ((unsigned)n & 7u)) << 4) + ((unsigned)k & 15u);
        wb[off] = v;
    }
}

// ---------------- stats for x: per-row mu/rstd + global gamma[0] ----------
__global__ void __launch_bounds__(256) stats_kernel(const float* __restrict__ x) {
    __shared__ unsigned sg;
    int tid = threadIdx.x;
    if (tid == 0) sg = 0u;
    __syncthreads();
    int warp = tid >> 5, lane = tid & 31;
    size_t row = (size_t)blockIdx.x * 8 + warp;
    const float* xr = x + row * DD;
    float4 a = *(const float4*)(xr + lane * 4);
    float4 b = *(const float4*)(xr + 128 + lane * 4);
    float s = ((a.x + a.y) + (a.z + a.w)) + ((b.x + b.y) + (b.z + b.w));
#pragma unroll
    for (int o = 16; o; o >>= 1) s += __shfl_xor_sync(0xffffffffu, s, o);
    float mu = s * (1.0f / 256.0f);
    float ss = 0.f, mx = 0.f, d;
    d = a.x - mu; ss += d * d; mx = fmaxf(mx, fabsf(d));
    d = a.y - mu; ss += d * d; mx = fmaxf(mx, fabsf(d));
    d = a.z - mu; ss += d * d; mx = fmaxf(mx, fabsf(d));
    d = a.w - mu; ss += d * d; mx = fmaxf(mx, fabsf(d));
    d = b.x - mu; ss += d * d; mx = fmaxf(mx, fabsf(d));
    d = b.y - mu; ss += d * d; mx = fmaxf(mx, fabsf(d));
    d = b.z - mu; ss += d * d; mx = fmaxf(mx, fabsf(d));
    d = b.w - mu; ss += d * d; mx = fmaxf(mx, fabsf(d));
#pragma unroll
    for (int o = 16; o; o >>= 1) {
        ss += __shfl_xor_sync(0xffffffffu, ss, o);
        mx  = fmaxf(mx, __shfl_xor_sync(0xffffffffu, mx, o));
    }
    float rsd = 1.0f / sqrtf(ss * (1.0f / 256.0f) + 1e-5f);
    if (lane == 0) {
        g_mu[0][row]   = mu;
        g_rstd[0][row] = rsd;
        atomicMax(&sg, __float_as_uint(mx * rsd));
    }
    __syncthreads();
    if (tid == 0) atomicMax(&g_gamma[0], sg);
}

// ---------------- fused layer: LN+quant -> IMMA (ldmatrix) -> epilogue ----
// CTA: 64 rows x 256 cols, K=256. 256 threads = 8 warps (2M x 4N), warp 32x64.
// smem: stats 4KB | sgmax | A int8 16KB @4352 | B int8 64KB @20736. 86272 B.
// 2 CTAs / SM.
template <int L>
__global__ void __launch_bounds__(256, 2) layer_kernel(const float* __restrict__ xin,
                                                       float* __restrict__ fout) {
    constexpr bool LAST = (L == 2);
    extern __shared__ char smem[];
    float*    rsum  = (float*)smem;                 // [4][64]
    float*    rsq   = rsum + 256;
    float*    rvx   = rsq + 256;
    float*    rvn   = rvx + 256;
    unsigned* sgmax = (unsigned*)(smem + 4096);
    char*     Asm   = smem + 4352;
    char*     Bsm   = smem + 20736;
    const uint32_t A_u = smem_u32(Asm);
    const uint32_t B_u = smem_u32(Bsm);

    const int tid = threadIdx.x;
    const int warp = tid >> 5, lane = tid & 31;
    const int row0 = blockIdx.x * 64;

    if (tid == 0) *sgmax = 0u;

    const float gamma  = fmaxf(__uint_as_float(g_gamma[L]), 1e-8f);
    const float qs     = 127.0f / gamma;
    const float oscale = g_beta[L] * gamma / 127.0f;
    float poscale = 0.f;
    if (L > 0) poscale = g_beta[L - 1] * fmaxf(__uint_as_float(g_gamma[L - 1]), 1e-8f) / 127.0f;

    const short* sprev = (L == 1) ? g_hs1 : g_hs2;
    const float* muL = g_mu[L];
    const float* rsL = g_rstd[L];

    // ---- B copy: 64KB pre-swizzled +-1 int8 (hot in L2) ----
    {
        const uint4* src = (const uint4*)(g_wb[L]);
        uint4* dst = (uint4*)Bsm;
#pragma unroll
        for (int i = 0; i < 16; ++i) dst[tid + i * 256] = src[tid + i * 256];
    }

    // ---- A: load -> LN -> quantize int8 -> swizzled smem (16B chunks) ----
#pragma unroll
    for (int it = 0; it < 4; ++it) {
        int c = tid + it * 256;           // chunk id, 1024 total (64 rows x 16 chunks)
        int r = c >> 4, ch = c & 15;
        int grow = row0 + r;
        float mu = muL[grow], rsd = rsL[grow];
        float v[16];
        if (L == 0) {
            const float* p = xin + (size_t)grow * DD + ch * 16;
#pragma unroll
            for (int q = 0; q < 4; ++q) {
                float4 f = *(const float4*)(p + q * 4);
                v[4 * q] = f.x; v[4 * q + 1] = f.y; v[4 * q + 2] = f.z; v[4 * q + 3] = f.w;
            }
        } else {
            const short* p = sprev + (size_t)grow * DD + ch * 16;
#pragma unroll
            for (int q = 0; q < 2; ++q) {
                uint4 u = *(const uint4*)(p + q * 8);
                v[8 * q + 0] = (float)(short)(u.x & 0xFFFF) * poscale;
                v[8 * q + 1] = (float)(short)(u.x >> 16)    * poscale;
                v[8 * q + 2] = (float)(short)(u.y & 0xFFFF) * poscale;
                v[8 * q + 3] = (float)(short)(u.y >> 16)    * poscale;
                v[8 * q + 4] = (float)(short)(u.z & 0xFFFF) * poscale;
                v[8 * q + 5] = (float)(short)(u.z >> 16)    * poscale;
                v[8 * q + 6] = (float)(short)(u.w & 0xFFFF) * poscale;
                v[8 * q + 7] = (float)(short)(u.w >> 16)    * poscale;
            }
        }
        unsigned pk[4];
#pragma unroll
        for (int q = 0; q < 4; ++q) {
            unsigned w = 0;
#pragma unroll
            for (int b = 0; b < 4; ++b) {
                float xn = (v[4 * q + b] - mu) * rsd;
                int qi = __float2int_rn(fminf(fmaxf(xn * qs, -127.f), 127.f));
                w |= ((unsigned)qi & 0xFFu) << (8 * b);
            }
            pk[q] = w;
        }
        unsigned off = (unsigned)r * 256u + ((((unsigned)ch) ^ ((unsigned)r & 7u)) << 4);
        *(uint4*)(Asm + off) = make_uint4(pk[0], pk[1], pk[2], pk[3]);
    }
    __syncthreads();

    // ---- MMA mainloop: warp tile 32(M) x 64(N), K=256 in 8 k32 steps ----
    const int wm = warp & 1;        // 2 M-groups of 32 rows
    const int wn = warp >> 1;       // 4 N-groups of 64 cols

    uint32_t a_base[2]; unsigned a_x7[2];
#pragma unroll
    for (int i = 0; i < 2; ++i) {
        int r = wm * 32 + i * 16 + (lane & 15);
        a_base[i] = A_u + (unsigned)r * 256u;
        a_x7[i] = (unsigned)r & 7u;
    }
    uint32_t b_base[4]; unsigned b_x7[4];
#pragma unroll
    for (int jp = 0; jp < 4; ++jp) {
        int n = wn * 64 + jp * 16 + ((lane >> 4) << 3) + (lane & 7);
        b_base[jp] = B_u + (unsigned)n * 256u;
        b_x7[jp] = (unsigned)n & 7u;
    }
    const unsigned a_ck = (unsigned)(lane >> 4);        // 0/1: k16-half
    const unsigned b_ck = (unsigned)((lane >> 3) & 1);  // 0/1

    int acc[2][8][4];
#pragma unroll
    for (int i = 0; i < 2; i++)
#pragma unroll
        for (int j = 0; j < 8; j++)
#pragma unroll
            for (int r = 0; r < 4; r++) acc[i][j][r] = 0;

#pragma unroll
    for (int kk = 0; kk < 8; ++kk) {
        unsigned a[2][4];
#pragma unroll
        for (int i = 0; i < 2; ++i) {
            uint32_t ad = a_base[i] + ((((unsigned)(kk * 2) + a_ck) ^ a_x7[i]) << 4);
            asm volatile("ldmatrix.sync.aligned.m8n8.x4.shared.b16 {%0,%1,%2,%3}, [%4];"
                         : "=r"(a[i][0]), "=r"(a[i][1]), "=r"(a[i][2]), "=r"(a[i][3])
                         : "r"(ad));
        }
#pragma unroll
        for (int jp = 0; jp < 4; ++jp) {
            uint32_t bd = b_base[jp] + ((((unsigned)(kk * 2) + b_ck) ^ b_x7[jp]) << 4);
            unsigned rb[4];
            asm volatile("ldmatrix.sync.aligned.m8n8.x4.shared.b16 {%0,%1,%2,%3}, [%4];"
                         : "=r"(rb[0]), "=r"(rb[1]), "=r"(rb[2]), "=r"(rb[3])
                         : "r"(bd));
#pragma unroll
            for (int i = 0; i < 2; ++i) {
                asm volatile(
                    "mma.sync.aligned.m16n8k32.row.col.s32.s8.s8.s32 "
                    "{%0,%1,%2,%3}, {%4,%5,%6,%7}, {%8,%9}, {%0,%1,%2,%3};\n"
                    : "+r"(acc[i][2 * jp][0]), "+r"(acc[i][2 * jp][1]),
                      "+r"(acc[i][2 * jp][2]), "+r"(acc[i][2 * jp][3])
                    : "r"(a[i][0]), "r"(a[i][1]), "r"(a[i][2]), "r"(a[i][3]),
                      "r"(rb[0]), "r"(rb[1]));
                asm volatile(
                    "mma.sync.aligned.m16n8k32.row.col.s32.s8.s8.s32 "
                    "{%0,%1,%2,%3}, {%4,%5,%6,%7}, {%8,%9}, {%0,%1,%2,%3};\n"
                    : "+r"(acc[i][2 * jp + 1][0]), "+r"(acc[i][2 * jp + 1][1]),
                      "+r"(acc[i][2 * jp + 1][2]), "+r"(acc[i][2 * jp + 1][3])
                    : "r"(a[i][0]), "r"(a[i][1]), "r"(a[i][2]), "r"(a[i][3]),
                      "r"(rb[2]), "r"(rb[3]));
            }
        }
    }

    // ---- epilogue: scale (+relu), store, fused next-layer LN stats ----
    const int qrow = lane >> 2, tig = lane & 3;
    short* outs = (L == 0) ? g_hs1 : g_hs2;

#pragma unroll
    for (int i = 0; i < 2; ++i) {
#pragma unroll
        for (int hi = 0; hi < 2; ++hi) {
            int lr = wm * 32 + i * 16 + hi * 8 + qrow;
            int grow = row0 + lr;
            if (!LAST) {
                float s1 = 0.f, s2 = 0.f, vmx = 0.f, vmn = 3.4e38f;
#pragma unroll
                for (int j = 0; j < 8; ++j) {
                    int q0 = max(acc[i][j][hi * 2], 0);       // exact int <= 32512
                    int q1 = max(acc[i][j][hi * 2 + 1], 0);
                    float v0 = (float)q0 * oscale;
                    float v1 = (float)q1 * oscale;
                    s1 += v0 + v1;
                    s2 += v0 * v0 + v1 * v1;
                    vmx = fmaxf(vmx, fmaxf(v0, v1));
                    vmn = fminf(vmn, fminf(v0, v1));
                    int col = wn * 64 + j * 8 + tig * 2;
                    *(unsigned*)(outs + (size_t)grow * DD + col) =
                        (unsigned)(q0 & 0xFFFF) | ((unsigned)q1 << 16);
                }
                s1 += __shfl_xor_sync(0xffffffffu, s1, 1);
                s1 += __shfl_xor_sync(0xffffffffu, s1, 2);
                s2 += __shfl_xor_sync(0xffffffffu, s2, 1);
                s2 += __shfl_xor_sync(0xffffffffu, s2, 2);
                vmx = fmaxf(vmx, __shfl_xor_sync(0xffffffffu, vmx, 1));
                vmx = fmaxf(vmx, __shfl_xor_sync(0xffffffffu, vmx, 2));
                vmn = fminf(vmn, __shfl_xor_sync(0xffffffffu, vmn, 1));
                vmn = fminf(vmn, __shfl_xor_sync(0xffffffffu, vmn, 2));
                if (tig == 0) {
                    rsum[wn * 64 + lr] = s1;
                    rsq [wn * 64 + lr] = s2;
                    rvx [wn * 64 + lr] = vmx;
                    rvn [wn * 64 + lr] = vmn;
                }
            } else {
#pragma unroll
                for (int j = 0; j < 8; ++j) {
                    float v0 = (float)acc[i][j][hi * 2]     * oscale;
                    float v1 = (float)acc[i][j][hi * 2 + 1] * oscale;
                    int col = wn * 64 + j * 8 + tig * 2;
                    *(float2*)(fout + (size_t)grow * DD + col) = make_float2(v0, v1);
                }
            }
        }
    }

    if constexpr (!LAST) {
        __syncthreads();
        if (tid < 64) {
            float a1 = (rsum[tid] + rsum[64 + tid]) + (rsum[128 + tid] + rsum[192 + tid]);
            float a2 = (rsq[tid]  + rsq[64 + tid])  + (rsq[128 + tid]  + rsq[192 + tid]);
            float mx = fmaxf(fmaxf(rvx[tid], rvx[64 + tid]), fmaxf(rvx[128 + tid], rvx[192 + tid]));
            float mn = fminf(fminf(rvn[tid], rvn[64 + tid]), fminf(rvn[128 + tid], rvn[192 + tid]));
            float mu  = a1 * (1.0f / 256.0f);
            float var = fmaxf(a2 * (1.0f / 256.0f) - mu * mu, 0.0f);
            float rsd = 1.0f / sqrtf(var + 1e-5f);
            g_mu[L + 1][row0 + tid]   = mu;
            g_rstd[L + 1][row0 + tid] = rsd;
            unsigned gu = __float_as_uint(fmaxf(mx - mu, mu - mn) * rsd);
#pragma unroll
            for (int o = 16; o; o >>= 1) gu = max(gu, __shfl_xor_sync(0xffffffffu, gu, o));
            if ((tid & 31) == 0) atomicMax(sgmax, gu);
        }
        __syncthreads();
        if (tid == 0) atomicMax(&g_gamma[L + 1], *sgmax);
    }
}

// ---------------- launch ----------------
extern "C" void kernel_launch(void* const* d_in, const int* in_sizes, int n_in,
                              void* d_out, int out_size) {
    const float* x  = (const float*)d_in[0];
    const float* W1 = (const float*)d_in[1];
    const float* W2 = (const float*)d_in[2];
    const float* W3 = (const float*)d_in[3];
    float* out = (float*)d_out;

    constexpr int SMEM = 20736 + 65536;  // 86272 B
    cudaFuncSetAttribute(layer_kernel<0>, cudaFuncAttributeMaxDynamicSharedMemorySize, SMEM);
    cudaFuncSetAttribute(layer_kernel<1>, cudaFuncAttributeMaxDynamicSharedMemorySize, SMEM);
    cudaFuncSetAttribute(layer_kernel<2>, cudaFuncAttributeMaxDynamicSharedMemorySize, SMEM);

    init_kernel<<<1, 32>>>();
    wprep_kernel<<<3, 1024>>>(W1, W2, W3);
    stats_kernel<<<BN / 8, 256>>>(x);
    layer_kernel<0><<<BN / 64, 256, SMEM>>>(x, nullptr);
    layer_kernel<1><<<BN / 64, 256, SMEM>>>(nullptr, nullptr);
    layer_kernel<2><<<BN / 64, 256, SMEM>>>(nullptr, out);
}

// round 12
// speedup vs baseline: 1.6048x; 1.0015x over previous
#include <cuda_runtime.h>
#include <cuda_bf16.h>
#include <math.h>
#include <stdint.h>

#define BN 131072
#define DD 256

// ---------------- scratch (device globals: allocation-free) ----------------
__device__ __align__(16) short       g_hs1[(size_t)BN * DD];   // layer0 out (int16, exact)
__device__ __align__(16) short       g_hs2[(size_t)BN * DD];   // layer1 out
__device__ float                     g_mu[3][BN];
__device__ float                     g_rstd[3][BN];
__device__ unsigned                  g_gamma[3];
__device__ float                     g_beta[3];
__device__ __align__(16) signed char g_wb[3][DD * DD];         // +-1 int8, swizzled [n][k] layout

__device__ __forceinline__ uint32_t smem_u32(const void* p) {
    uint32_t a;
    asm("{ .reg .u64 t; cvta.to.shared.u64 t, %1; cvt.u32.u64 %0, t; }" : "=r"(a) : "l"(p));
    return a;
}

// ---------------- init ----------------
__global__ void init_kernel() {
    if (threadIdx.x < 3) g_gamma[threadIdx.x] = 0u;
}

// ---------------- weight prep: alpha/beta + sign -> swizzled int8 ---------
// Layout: row n (256 B of k), chunk c (16B) stored at chunk (c ^ (n&7)).
__global__ void __launch_bounds__(1024) wprep_kernel(const float* __restrict__ W1,
                                                     const float* __restrict__ W2,
                                                     const float* __restrict__ W3) {
    const float* W = blockIdx.x == 0 ? W1 : (blockIdx.x == 1 ? W2 : W3);
    __shared__ float ps[32], pa[32];
    __shared__ float s_alpha;
    int tid = threadIdx.x;
    float s = 0.f, sa = 0.f;
    for (int i = tid; i < DD * DD; i += 1024) {
        float w = W[i];
        s += w; sa += fabsf(w);
    }
#pragma unroll
    for (int o = 16; o; o >>= 1) {
        s  += __shfl_xor_sync(0xffffffffu, s,  o);
        sa += __shfl_xor_sync(0xffffffffu, sa, o);
    }
    if ((tid & 31) == 0) { ps[tid >> 5] = s; pa[tid >> 5] = sa; }
    __syncthreads();
    if (tid == 0) {
        float ts = 0.f, ta = 0.f;
        for (int i = 0; i < 32; i++) { ts += ps[i]; ta += pa[i]; }  // fixed order
        float alpha = ts / 65536.0f;
        g_beta[blockIdx.x] = fmaxf(ta / 65536.0f, 1e-8f);
        s_alpha = alpha;
    }
    __syncthreads();
    float alpha = s_alpha;
    signed char* wb = g_wb[blockIdx.x];
    for (int i = tid; i < DD * DD; i += 1024) {
        int n = i >> 8, k = i & 255;
        signed char v = ((W[i] - alpha) > 0.f) ? (signed char)1 : (signed char)-1;
        unsigned off = (unsigned)n * 256u + ((((unsigned)k >> 4) ^ ((unsigned)n & 7u)) << 4) + ((unsigned)k & 15u);
        wb[off] = v;
    }
}

// ---------------- stats for x: per-row mu/rstd + global gamma[0] ----------
__global__ void __launch_bounds__(256) stats_kernel(const float* __restrict__ x) {
    __shared__ unsigned sg;
    int tid = threadIdx.x;
    if (tid == 0) sg = 0u;
    __syncthreads();
    int warp = tid >> 5, lane = tid & 31;
    size_t row = (size_t)blockIdx.x * 8 + warp;
    const float* xr = x + row * DD;
    float4 a = *(const float4*)(xr + lane * 4);
    float4 b = *(const float4*)(xr + 128 + lane * 4);
    float s = ((a.x + a.y) + (a.z + a.w)) + ((b.x + b.y) + (b.z + b.w));
#pragma unroll
    for (int o = 16; o; o >>= 1) s += __shfl_xor_sync(0xffffffffu, s, o);
    float mu = s * (1.0f / 256.0f);
    float ss = 0.f, mx = 0.f, d;
    d = a.x - mu; ss += d * d; mx = fmaxf(mx, fabsf(d));
    d = a.y - mu; ss += d * d; mx = fmaxf(mx, fabsf(d));
    d = a.z - mu; ss += d * d; mx = fmaxf(mx, fabsf(d));
    d = a.w - mu; ss += d * d; mx = fmaxf(mx, fabsf(d));
    d = b.x - mu; ss += d * d; mx = fmaxf(mx, fabsf(d));
    d = b.y - mu; ss += d * d; mx = fmaxf(mx, fabsf(d));
    d = b.z - mu; ss += d * d; mx = fmaxf(mx, fabsf(d));
    d = b.w - mu; ss += d * d; mx = fmaxf(mx, fabsf(d));
#pragma unroll
    for (int o = 16; o; o >>= 1) {
        ss += __shfl_xor_sync(0xffffffffu, ss, o);
        mx  = fmaxf(mx, __shfl_xor_sync(0xffffffffu, mx, o));
    }
    float rsd = 1.0f / sqrtf(ss * (1.0f / 256.0f) + 1e-5f);
    if (lane == 0) {
        g_mu[0][row]   = mu;
        g_rstd[0][row] = rsd;
        atomicMax(&sg, __float_as_uint(mx * rsd));
    }
    __syncthreads();
    if (tid == 0) atomicMax(&g_gamma[0], sg);
}

// ---------------- fused layer: LN+quant -> IMMA (ldmatrix) -> epilogue ----
// CTA: 64 rows x 256 cols, K=256. 256 threads = 8 warps (2M x 4N), warp 32x64.
// smem: stats 4KB | sgmax | A int8 16KB @4352 | B int8 64KB @20736. 86272 B.
// 2 CTAs / SM.
template <int L>
__global__ void __launch_bounds__(256, 2) layer_kernel(const float* __restrict__ xin,
                                                       float* __restrict__ fout) {
    constexpr bool LAST = (L == 2);
    extern __shared__ char smem[];
    float*    rsum  = (float*)smem;                 // [4][64]
    float*    rsq   = rsum + 256;
    float*    rvx   = rsq + 256;
    float*    rvn   = rvx + 256;
    unsigned* sgmax = (unsigned*)(smem + 4096);
    char*     Asm   = smem + 4352;
    char*     Bsm   = smem + 20736;
    const uint32_t A_u = smem_u32(Asm);
    const uint32_t B_u = smem_u32(Bsm);

    const int tid = threadIdx.x;
    const int warp = tid >> 5, lane = tid & 31;
    const int row0 = blockIdx.x * 64;

    if (tid == 0) *sgmax = 0u;

    const float gamma  = fmaxf(__uint_as_float(g_gamma[L]), 1e-8f);
    const float qs     = 127.0f / gamma;
    const float oscale = g_beta[L] * gamma / 127.0f;
    float poscale = 0.f;
    if (L > 0) poscale = g_beta[L - 1] * fmaxf(__uint_as_float(g_gamma[L - 1]), 1e-8f) / 127.0f;

    const short* sprev = (L == 1) ? g_hs1 : g_hs2;
    const float* muL = g_mu[L];
    const float* rsL = g_rstd[L];

    // ---- B copy: 64KB pre-swizzled +-1 int8 (hot in L2) ----
    {
        const uint4* src = (const uint4*)(g_wb[L]);
        uint4* dst = (uint4*)Bsm;
#pragma unroll
        for (int i = 0; i < 16; ++i) dst[tid + i * 256] = src[tid + i * 256];
    }

    // ---- A: load -> LN -> quantize int8 -> swizzled smem (16B chunks) ----
#pragma unroll
    for (int it = 0; it < 4; ++it) {
        int c = tid + it * 256;           // chunk id, 1024 total (64 rows x 16 chunks)
        int r = c >> 4, ch = c & 15;
        int grow = row0 + r;
        float mu = muL[grow], rsd = rsL[grow];
        float v[16];
        if (L == 0) {
            const float* p = xin + (size_t)grow * DD + ch * 16;
#pragma unroll
            for (int q = 0; q < 4; ++q) {
                float4 f = *(const float4*)(p + q * 4);
                v[4 * q] = f.x; v[4 * q + 1] = f.y; v[4 * q + 2] = f.z; v[4 * q + 3] = f.w;
            }
        } else {
            const short* p = sprev + (size_t)grow * DD + ch * 16;
#pragma unroll
            for (int q = 0; q < 2; ++q) {
                uint4 u = *(const uint4*)(p + q * 8);
                v[8 * q + 0] = (float)(short)(u.x & 0xFFFF) * poscale;
                v[8 * q + 1] = (float)(short)(u.x >> 16)    * poscale;
                v[8 * q + 2] = (float)(short)(u.y & 0xFFFF) * poscale;
                v[8 * q + 3] = (float)(short)(u.y >> 16)    * poscale;
                v[8 * q + 4] = (float)(short)(u.z & 0xFFFF) * poscale;
                v[8 * q + 5] = (float)(short)(u.z >> 16)    * poscale;
                v[8 * q + 6] = (float)(short)(u.w & 0xFFFF) * poscale;
                v[8 * q + 7] = (float)(short)(u.w >> 16)    * poscale;
            }
        }
        unsigned pk[4];
#pragma unroll
        for (int q = 0; q < 4; ++q) {
            unsigned w = 0;
#pragma unroll
            for (int b = 0; b < 4; ++b) {
                float xn = (v[4 * q + b] - mu) * rsd;
                int qi = __float2int_rn(fminf(fmaxf(xn * qs, -127.f), 127.f));
                w |= ((unsigned)qi & 0xFFu) << (8 * b);
            }
            pk[q] = w;
        }
        unsigned off = (unsigned)r * 256u + ((((unsigned)ch) ^ ((unsigned)r & 7u)) << 4);
        *(uint4*)(Asm + off) = make_uint4(pk[0], pk[1], pk[2], pk[3]);
    }
    __syncthreads();

    // ---- MMA mainloop: warp tile 32(M) x 64(N), K=256 in 8 k32 steps ----
    const int wm = warp & 1;        // 2 M-groups of 32 rows
    const int wn = warp >> 1;       // 4 N-groups of 64 cols

    uint32_t a_base[2]; unsigned a_x7[2];
#pragma unroll
    for (int i = 0; i < 2; ++i) {
        int r = wm * 32 + i * 16 + (lane & 15);
        a_base[i] = A_u + (unsigned)r * 256u;
        a_x7[i] = (unsigned)r & 7u;
    }
    uint32_t b_base[4]; unsigned b_x7[4];
#pragma unroll
    for (int jp = 0; jp < 4; ++jp) {
        int n = wn * 64 + jp * 16 + ((lane >> 4) << 3) + (lane & 7);
        b_base[jp] = B_u + (unsigned)n * 256u;
        b_x7[jp] = (unsigned)n & 7u;
    }
    const unsigned a_ck = (unsigned)(lane >> 4);        // 0/1: k16-half
    const unsigned b_ck = (unsigned)((lane >> 3) & 1);  // 0/1

    int acc[2][8][4];
#pragma unroll
    for (int i = 0; i < 2; i++)
#pragma unroll
        for (int j = 0; j < 8; j++)
#pragma unroll
            for (int r = 0; r < 4; r++) acc[i][j][r] = 0;

#pragma unroll
    for (int kk = 0; kk < 8; ++kk) {
        unsigned a[2][4];
#pragma unroll
        for (int i = 0; i < 2; ++i) {
            uint32_t ad = a_base[i] + ((((unsigned)(kk * 2) + a_ck) ^ a_x7[i]) << 4);
            asm volatile("ldmatrix.sync.aligned.m8n8.x4.shared.b16 {%0,%1,%2,%3}, [%4];"
                         : "=r"(a[i][0]), "=r"(a[i][1]), "=r"(a[i][2]), "=r"(a[i][3])
                         : "r"(ad));
        }
#pragma unroll
        for (int jp = 0; jp < 4; ++jp) {
            uint32_t bd = b_base[jp] + ((((unsigned)(kk * 2) + b_ck) ^ b_x7[jp]) << 4);
            unsigned rb[4];
            asm volatile("ldmatrix.sync.aligned.m8n8.x4.shared.b16 {%0,%1,%2,%3}, [%4];"
                         : "=r"(rb[0]), "=r"(rb[1]), "=r"(rb[2]), "=r"(rb[3])
                         : "r"(bd));
#pragma unroll
            for (int i = 0; i < 2; ++i) {
                asm volatile(
                    "mma.sync.aligned.m16n8k32.row.col.s32.s8.s8.s32 "
                    "{%0,%1,%2,%3}, {%4,%5,%6,%7}, {%8,%9}, {%0,%1,%2,%3};\n"
                    : "+r"(acc[i][2 * jp][0]), "+r"(acc[i][2 * jp][1]),
                      "+r"(acc[i][2 * jp][2]), "+r"(acc[i][2 * jp][3])
                    : "r"(a[i][0]), "r"(a[i][1]), "r"(a[i][2]), "r"(a[i][3]),
                      "r"(rb[0]), "r"(rb[1]));
                asm volatile(
                    "mma.sync.aligned.m16n8k32.row.col.s32.s8.s8.s32 "
                    "{%0,%1,%2,%3}, {%4,%5,%6,%7}, {%8,%9}, {%0,%1,%2,%3};\n"
                    : "+r"(acc[i][2 * jp + 1][0]), "+r"(acc[i][2 * jp + 1][1]),
                      "+r"(acc[i][2 * jp + 1][2]), "+r"(acc[i][2 * jp + 1][3])
                    : "r"(a[i][0]), "r"(a[i][1]), "r"(a[i][2]), "r"(a[i][3]),
                      "r"(rb[2]), "r"(rb[3]));
            }
        }
    }

    // ---- epilogue: scale (+relu), store, fused next-layer LN stats ----
    const int qrow = lane >> 2, tig = lane & 3;
    short* outs = (L == 0) ? g_hs1 : g_hs2;

#pragma unroll
    for (int i = 0; i < 2; ++i) {
#pragma unroll
        for (int hi = 0; hi < 2; ++hi) {
            int lr = wm * 32 + i * 16 + hi * 8 + qrow;
            int grow = row0 + lr;
            if (!LAST) {
                float s1 = 0.f, s2 = 0.f, vmx = 0.f, vmn = 3.4e38f;
#pragma unroll
                for (int j = 0; j < 8; ++j) {
                    int q0 = max(acc[i][j][hi * 2], 0);       // exact int <= 32512
                    int q1 = max(acc[i][j][hi * 2 + 1], 0);
                    float v0 = (float)q0 * oscale;
                    float v1 = (float)q1 * oscale;
                    s1 += v0 + v1;
                    s2 += v0 * v0 + v1 * v1;
                    vmx = fmaxf(vmx, fmaxf(v0, v1));
                    vmn = fminf(vmn, fminf(v0, v1));
                    int col = wn * 64 + j * 8 + tig * 2;
                    *(unsigned*)(outs + (size_t)grow * DD + col) =
                        (unsigned)(q0 & 0xFFFF) | ((unsigned)q1 << 16);
                }
                s1 += __shfl_xor_sync(0xffffffffu, s1, 1);
                s1 += __shfl_xor_sync(0xffffffffu, s1, 2);
                s2 += __shfl_xor_sync(0xffffffffu, s2, 1);
                s2 += __shfl_xor_sync(0xffffffffu, s2, 2);
                vmx = fmaxf(vmx, __shfl_xor_sync(0xffffffffu, vmx, 1));
                vmx = fmaxf(vmx, __shfl_xor_sync(0xffffffffu, vmx, 2));
                vmn = fminf(vmn, __shfl_xor_sync(0xffffffffu, vmn, 1));
                vmn = fminf(vmn, __shfl_xor_sync(0xffffffffu, vmn, 2));
                if (tig == 0) {
                    rsum[wn * 64 + lr] = s1;
                    rsq [wn * 64 + lr] = s2;
                    rvx [wn * 64 + lr] = vmx;
                    rvn [wn * 64 + lr] = vmn;
                }
            } else {
#pragma unroll
                for (int j = 0; j < 8; ++j) {
                    float v0 = (float)acc[i][j][hi * 2]     * oscale;
                    float v1 = (float)acc[i][j][hi * 2 + 1] * oscale;
                    int col = wn * 64 + j * 8 + tig * 2;
                    *(float2*)(fout + (size_t)grow * DD + col) = make_float2(v0, v1);
                }
            }
        }
    }

    if constexpr (!LAST) {
        __syncthreads();
        if (tid < 64) {
            float a1 = (rsum[tid] + rsum[64 + tid]) + (rsum[128 + tid] + rsum[192 + tid]);
            float a2 = (rsq[tid]  + rsq[64 + tid])  + (rsq[128 + tid]  + rsq[192 + tid]);
            float mx = fmaxf(fmaxf(rvx[tid], rvx[64 + tid]), fmaxf(rvx[128 + tid], rvx[192 + tid]));
            float mn = fminf(fminf(rvn[tid], rvn[64 + tid]), fminf(rvn[128 + tid], rvn[192 + tid]));
            float mu  = a1 * (1.0f / 256.0f);
            float var = fmaxf(a2 * (1.0f / 256.0f) - mu * mu, 0.0f);
            float rsd = 1.0f / sqrtf(var + 1e-5f);
            g_mu[L + 1][row0 + tid]   = mu;
            g_rstd[L + 1][row0 + tid] = rsd;
            unsigned gu = __float_as_uint(fmaxf(mx - mu, mu - mn) * rsd);
#pragma unroll
            for (int o = 16; o; o >>= 1) gu = max(gu, __shfl_xor_sync(0xffffffffu, gu, o));
            if ((tid & 31) == 0) atomicMax(sgmax, gu);
        }
        __syncthreads();
        if (tid == 0) atomicMax(&g_gamma[L + 1], *sgmax);
    }
}

// ---------------- launch ----------------
extern "C" void kernel_launch(void* const* d_in, const int* in_sizes, int n_in,
                              void* d_out, int out_size) {
    const float* x  = (const float*)d_in[0];
    const float* W1 = (const float*)d_in[1];
    const float* W2 = (const float*)d_in[2];
    const float* W3 = (const float*)d_in[3];
    float* out = (float*)d_out;

    constexpr int SMEM = 20736 + 65536;  // 86272 B
    cudaFuncSetAttribute(layer_kernel<0>, cudaFuncAttributeMaxDynamicSharedMemorySize, SMEM);
    cudaFuncSetAttribute(layer_kernel<1>, cudaFuncAttributeMaxDynamicSharedMemorySize, SMEM);
    cudaFuncSetAttribute(layer_kernel<2>, cudaFuncAttributeMaxDynamicSharedMemorySize, SMEM);

    init_kernel<<<1, 32>>>();
    wprep_kernel<<<3, 1024>>>(W1, W2, W3);
    stats_kernel<<<BN / 8, 256>>>(x);
    layer_kernel<0><<<BN / 64, 256, SMEM>>>(x, nullptr);
    layer_kernel<1><<<BN / 64, 256, SMEM>>>(nullptr, nullptr);
    layer_kernel<2><<<BN / 64, 256, SMEM>>>(nullptr, out);
}